// round 11
// baseline (speedup 1.0000x reference)
#include <cuda_runtime.h>
#include <cstdint>

#define N_NODES 128
#define V_PTS   2048
#define XYZ     63
#define NG      9          // node groups: 8 groups of 15 + 1 group of 8

// ---- output layout ----
#define OFF_C      0
#define OFF_D      6144
#define OFF_EI     8192
#define OFF_DELTA  12288
#define OFF_MEAN   12672
#define OFF_LOGVAR 13696

// ---- scratch ----
__device__ float g_ei[N_NODES * 32];
__device__ float g_b1eff[N_NODES * 64];
__device__ float g_e[N_NODES * V_PTS];
__device__ float g_fpart[NG * V_PTS * 256];
// per-node packed weight image: tf32-rounded, K-interleaved, stride-72 rows
// W1 [64x72]=4608 | W2 4608 | W3 4608 | W4 [256x72]=18432 => 32256 floats = 8064 float4
__device__ float4 g_Wpad4[N_NODES * 8064];

// ---- field smem layout (float offsets) ----
#define F_BUFA 0        // 128 x 72 activation buffer (K-interleaved)
#define F_BUFB 9216
#define F_W1   18432    // 64 x 72
#define F_W2   23040
#define F_W3   27648
#define F_W4   32256    // 256 x 72
#define F_B1   50688
#define F_B2   50752
#define F_B3   50816
#define F_B4   50880
#define F_E    51136
#define F_TOT  51264    // 205056 bytes

// K-interleave within each 8-column group: pairs (k, k+4) become adjacent.
__device__ __forceinline__ int permk(int k) {   // storage position of original col k
    return (k & ~7) | (((k & 3) << 1) | ((k & 4) >> 2));
}
__device__ __forceinline__ int invk(int s) {    // original col stored at position s
    return (s & ~7) | (((s & 1) << 2) | ((s & 6) >> 1));
}

__device__ __forceinline__ float to_tf32(float x) {
    uint32_t r;
    asm("cvt.rna.tf32.f32 %0, %1;" : "=r"(r) : "f"(x));
    return __uint_as_float(r);
}

__device__ __forceinline__ void mma_tf32(float c[4], uint32_t a0, uint32_t a1,
                                         uint32_t a2, uint32_t a3,
                                         uint32_t b0, uint32_t b1) {
    asm volatile(
        "mma.sync.aligned.m16n8k8.row.col.f32.tf32.tf32.f32 "
        "{%0,%1,%2,%3}, {%4,%5,%6,%7}, {%8,%9}, {%0,%1,%2,%3};"
        : "+f"(c[0]), "+f"(c[1]), "+f"(c[2]), "+f"(c[3])
        : "r"(a0), "r"(a1), "r"(a2), "r"(a3), "r"(b0), "r"(b1));
}

// one warp computes a 16x32 tile of C[128 x N] = A[128 x 64] * W[N x 64]^T
// K-interleaved layout: fragment pairs (k, k+4) are adjacent -> LDS.64 loads.
// conflict-free: stride 72 mod 32 = 8 banks per row step.
__device__ __forceinline__ void gemm16x32(const float* __restrict__ Ain,
                                          const float* __restrict__ Ws,
                                          int mb, int cb, int lane,
                                          float c[4][4]) {
    int r   = mb * 16 + (lane >> 2);
    int kk2 = (lane & 3) * 2;
    const float* ar0 = Ain + r * 72 + kk2;
    const float* ar1 = ar0 + 8 * 72;
    const float* bc  = Ws + (cb + (lane >> 2)) * 72 + kk2;
    #pragma unroll
    for (int k8 = 0; k8 < 8; k8++) {
        float2 a0 = *(const float2*)&ar0[k8 * 8];   // (A[r][kk], A[r][kk+4])
        float2 a1 = *(const float2*)&ar1[k8 * 8];   // (A[r+8][kk], A[r+8][kk+4])
        #pragma unroll
        for (int n8 = 0; n8 < 4; n8++) {
            float2 b = *(const float2*)&bc[n8 * 8 * 72 + k8 * 8];  // (W[n][kk], W[n][kk+4])
            mma_tf32(c[n8],
                     __float_as_uint(a0.x), __float_as_uint(a1.x),
                     __float_as_uint(a0.y), __float_as_uint(a1.y),
                     __float_as_uint(b.x),  __float_as_uint(b.y));
        }
    }
}

// =====================================================================
// Kernel A: encoder + decoder + effective L1 bias (fp32 exact)
// =====================================================================
__global__ void setup_kernel(
    const float* __restrict__ poses, const float* __restrict__ t_ped,
    const float* __restrict__ w,
    const float* __restrict__ Wec1, const float* __restrict__ bec1,
    const float* __restrict__ Wec21, const float* __restrict__ bec21,
    const float* __restrict__ Wec22, const float* __restrict__ bec22,
    const float* __restrict__ Wdc1, const float* __restrict__ bdc1,
    const float* __restrict__ Wdc21, const float* __restrict__ bdc21,
    const float* __restrict__ Wdc22, const float* __restrict__ bdc22,
    const float* __restrict__ Wf1, const float* __restrict__ bf1,
    float* __restrict__ out)
{
    int n = blockIdx.x;
    int t = threadIdx.x;
    __shared__ float s_in[88], s_net[64], s_mean[8], s_din[80], s_net2[64], s_ei[32];

    if (t < 72)       s_in[t] = w[n * 24 + t / 3] * poses[n * 72 + t];
    else if (t < 88)  s_in[t] = t_ped[t - 72];
    __syncthreads();

    if (t < 64) {
        float a = bec1[n * 64 + t];
        const float* Wr = &Wec1[(n * 64 + t) * 88];
        #pragma unroll 8
        for (int c = 0; c < 88; c++) a += Wr[c] * s_in[c];
        s_net[t] = fmaxf(a, 0.f);
    }
    __syncthreads();

    if (t < 8) {
        float m = bec21[n * 8 + t], lv = bec22[n * 8 + t];
        const float* Wm = &Wec21[(n * 8 + t) * 64];
        const float* Wl = &Wec22[(n * 8 + t) * 64];
        #pragma unroll 8
        for (int c = 0; c < 64; c++) { m += Wm[c] * s_net[c]; lv += Wl[c] * s_net[c]; }
        s_mean[t] = m;
        out[OFF_MEAN + n * 8 + t] = m;
        out[OFF_LOGVAR + n * 8 + t] = lv;
    }
    __syncthreads();

    if (t < 72)      s_din[t] = s_in[t];
    else if (t < 80) s_din[t] = s_mean[t - 72];
    __syncthreads();

    if (t < 64) {
        float a = bdc1[n * 64 + t];
        const float* Wr = &Wdc1[(n * 64 + t) * 80];
        #pragma unroll 8
        for (int c = 0; c < 80; c++) a += Wr[c] * s_din[c];
        s_net2[t] = fmaxf(a, 0.f);
    }
    __syncthreads();

    if (t < 32) {
        float a = bdc21[n * 32 + t];
        const float* Wr = &Wdc21[(n * 32 + t) * 64];
        #pragma unroll 8
        for (int c = 0; c < 64; c++) a += Wr[c] * s_net2[c];
        s_ei[t] = a;
        g_ei[n * 32 + t] = a;
        out[OFF_EI + n * 32 + t] = a;
    }
    if (t >= 32 && t < 35) {
        int j = t - 32;
        float a = bdc22[n * 3 + j];
        const float* Wr = &Wdc22[(n * 3 + j) * 64];
        #pragma unroll 8
        for (int c = 0; c < 64; c++) a += Wr[c] * s_net2[c];
        out[OFF_DELTA + n * 3 + j] = a;
    }
    __syncthreads();

    if (t < 64) {
        float a = bf1[n * 64 + t];
        const float* Wr = &Wf1[(size_t)(n * 64 + t) * 95];
        #pragma unroll 8
        for (int c = 0; c < 32; c++) a += Wr[c] * s_ei[c];
        g_b1eff[n * 64 + t] = a;
    }
}

// =====================================================================
// Kernel B: RBF blend weights, normalized (fp32 exact)
// =====================================================================
__global__ void bweight_kernel(const float* __restrict__ wpts,
                               const float* __restrict__ nodes_posed)
{
    int v = blockIdx.x * blockDim.x + threadIdx.x;
    if (v >= V_PTS) return;
    float px = wpts[v * 3 + 0], py = wpts[v * 3 + 1], pz = wpts[v * 3 + 2];
    float denom = 0.f;
    for (int n = 0; n < N_NODES; n++) {
        float dx = px - nodes_posed[n * 3 + 0];
        float dy = py - nodes_posed[n * 3 + 1];
        float dz = pz - nodes_posed[n * 3 + 2];
        float d2 = dx * dx + dy * dy + dz * dz;
        float influ = expf(-d2 * (1.0f / 0.18f)) - 0.01f;
        float e = (influ >= 0.f) ? (influ + 1e-7f) : 0.f;
        denom += fmaxf(influ, 0.f) + 1e-7f;
        g_e[n * V_PTS + v] = e;
    }
    float inv = 1.0f / denom;
    for (int n = 0; n < N_NODES; n++) g_e[n * V_PTS + v] *= inv;
}

// =====================================================================
// Kernel E: prepack weights -> tf32, K-interleaved, stride-72 rows
// =====================================================================
__global__ void prepack_kernel(const float* __restrict__ Wf1,
                               const float* __restrict__ Wf2,
                               const float* __restrict__ Wf3,
                               const float* __restrict__ Wf4)
{
    int n = blockIdx.x, tid = threadIdx.x;   // 256 threads
    float* dst = (float*)&g_Wpad4[(size_t)n * 8064];

    for (int i = tid; i < 4608; i += 256) {            // W1 [64 x 72]
        int j = i / 72, s = i - j * 72;
        float v = 0.f;
        if (s < 64) { int k = invk(s); if (k < XYZ) v = Wf1[(size_t)(n * 64 + j) * 95 + 32 + k]; }
        dst[i] = to_tf32(v);
    }
    for (int i = tid; i < 4608; i += 256) {            // W2
        int j = i / 72, s = i - j * 72;
        float v = 0.f;
        if (s < 64) v = Wf2[(size_t)n * 4096 + j * 64 + invk(s)];
        dst[4608 + i] = to_tf32(v);
    }
    for (int i = tid; i < 4608; i += 256) {            // W3
        int j = i / 72, s = i - j * 72;
        float v = 0.f;
        if (s < 64) v = Wf3[(size_t)n * 4096 + j * 64 + invk(s)];
        dst[9216 + i] = to_tf32(v);
    }
    for (int i = tid; i < 18432; i += 256) {           // W4 [256 x 72]
        int j = i / 72, s = i - j * 72;
        float v = 0.f;
        if (s < 64) v = Wf4[(size_t)n * 16384 + j * 64 + invk(s)];
        dst[13824 + i] = to_tf32(v);
    }
}

// =====================================================================
// Kernel C: feature field via mma.sync tf32 (HMMA)
// grid = (16 v-tiles) x (9 node-groups), 512 threads (16 warps)
// =====================================================================
__global__ void __launch_bounds__(512, 1) field_kernel(
    const float* __restrict__ local_coords,
    const float* __restrict__ bf2, const float* __restrict__ bf3,
    const float* __restrict__ bf4)
{
    extern __shared__ float sm[];
    int tid  = threadIdx.x;
    int wid  = tid >> 5, lane = tid & 31;
    int mb   = wid & 7;            // M-block (16 rows)
    int nhi  = wid >> 3;           // 0/1: which 32-col block within 64
    int v0 = blockIdx.x * 128;
    int g  = blockIdx.y;
    int n0 = g * 15;
    int ncnt = (g == 8) ? 8 : 15;

    // blend accumulator: rows (mb*16 + lane>>2) and +8; 32 cols per row-pair
    float acc[64];
    #pragma unroll
    for (int i = 0; i < 64; i++) acc[i] = 0.f;

    int r0 = mb * 16 + (lane >> 2);

    for (int ni = 0; ni < ncnt; ni++) {
        int n = n0 + ni;
        __syncthreads();   // previous node's reads done before overwrite

        // ---- stage weights (raw float4 copy of prepacked image) ----
        {
            const float4* src = &g_Wpad4[(size_t)n * 8064];
            float4* dst = ((float4*)sm) + (F_W1 / 4);
            #pragma unroll 4
            for (int i = tid; i < 8064; i += 512) dst[i] = src[i];
        }
        if (tid < 64) {
            sm[F_B1 + tid] = g_b1eff[n * 64 + tid];
            sm[F_B2 + tid] = bf2[n * 64 + tid];
            sm[F_B3 + tid] = bf3[n * 64 + tid];
        }
        if (tid < 256) sm[F_B4 + tid] = bf4[n * 256 + tid];
        if (tid < 128) sm[F_E + tid]  = g_e[(size_t)n * V_PTS + v0 + tid];
        // ---- stage A0 = lc tile [128 x 64] tf32, K-interleaved ----
        for (int i = tid; i < 8192; i += 512) {
            int v = i >> 6, s = i & 63;
            int k = invk(s);
            float val = (k < XYZ)
                ? local_coords[((size_t)n * V_PTS + v0 + v) * XYZ + k] : 0.f;
            sm[F_BUFA + v * 72 + s] = to_tf32(val);
        }
        __syncthreads();

        float ev0 = sm[F_E + r0];
        float ev1 = sm[F_E + r0 + 8];

        // ================= L1: bufA -> bufB =================
        {
            float c[4][4];
            #pragma unroll
            for (int a = 0; a < 4; a++)
                #pragma unroll
                for (int b = 0; b < 4; b++) c[a][b] = 0.f;
            int cb = nhi * 32;
            gemm16x32(sm + F_BUFA, sm + F_W1, mb, cb, lane, c);
            #pragma unroll
            for (int n8 = 0; n8 < 4; n8++) {
                int cc = cb + n8 * 8 + (lane & 3) * 2;
                int p0 = permk(cc), p1 = permk(cc + 1);
                float b0 = sm[F_B1 + cc], b1 = sm[F_B1 + cc + 1];
                sm[F_BUFB + r0 * 72 + p0]       = to_tf32(fmaxf(c[n8][0] + b0, 0.f));
                sm[F_BUFB + r0 * 72 + p1]       = to_tf32(fmaxf(c[n8][1] + b1, 0.f));
                sm[F_BUFB + (r0 + 8) * 72 + p0] = to_tf32(fmaxf(c[n8][2] + b0, 0.f));
                sm[F_BUFB + (r0 + 8) * 72 + p1] = to_tf32(fmaxf(c[n8][3] + b1, 0.f));
            }
        }
        __syncthreads();

        // ================= L2: bufB -> bufA =================
        {
            float c[4][4];
            #pragma unroll
            for (int a = 0; a < 4; a++)
                #pragma unroll
                for (int b = 0; b < 4; b++) c[a][b] = 0.f;
            int cb = nhi * 32;
            gemm16x32(sm + F_BUFB, sm + F_W2, mb, cb, lane, c);
            #pragma unroll
            for (int n8 = 0; n8 < 4; n8++) {
                int cc = cb + n8 * 8 + (lane & 3) * 2;
                int p0 = permk(cc), p1 = permk(cc + 1);
                float b0 = sm[F_B2 + cc], b1 = sm[F_B2 + cc + 1];
                sm[F_BUFA + r0 * 72 + p0]       = to_tf32(fmaxf(c[n8][0] + b0, 0.f));
                sm[F_BUFA + r0 * 72 + p1]       = to_tf32(fmaxf(c[n8][1] + b1, 0.f));
                sm[F_BUFA + (r0 + 8) * 72 + p0] = to_tf32(fmaxf(c[n8][2] + b0, 0.f));
                sm[F_BUFA + (r0 + 8) * 72 + p1] = to_tf32(fmaxf(c[n8][3] + b1, 0.f));
            }
        }
        __syncthreads();

        // ================= L3: bufA -> bufB =================
        {
            float c[4][4];
            #pragma unroll
            for (int a = 0; a < 4; a++)
                #pragma unroll
                for (int b = 0; b < 4; b++) c[a][b] = 0.f;
            int cb = nhi * 32;
            gemm16x32(sm + F_BUFA, sm + F_W3, mb, cb, lane, c);
            #pragma unroll
            for (int n8 = 0; n8 < 4; n8++) {
                int cc = cb + n8 * 8 + (lane & 3) * 2;
                int p0 = permk(cc), p1 = permk(cc + 1);
                float b0 = sm[F_B3 + cc], b1 = sm[F_B3 + cc + 1];
                sm[F_BUFB + r0 * 72 + p0]       = to_tf32(fmaxf(c[n8][0] + b0, 0.f));
                sm[F_BUFB + r0 * 72 + p1]       = to_tf32(fmaxf(c[n8][1] + b1, 0.f));
                sm[F_BUFB + (r0 + 8) * 72 + p0] = to_tf32(fmaxf(c[n8][2] + b0, 0.f));
                sm[F_BUFB + (r0 + 8) * 72 + p1] = to_tf32(fmaxf(c[n8][3] + b1, 0.f));
            }
        }
        __syncthreads();

        // ================= L4: bufB x W4 (256 cols, 4 rounds) =================
        #pragma unroll
        for (int rnd = 0; rnd < 4; rnd++) {
            float c[4][4];
            #pragma unroll
            for (int a = 0; a < 4; a++)
                #pragma unroll
                for (int b = 0; b < 4; b++) c[a][b] = 0.f;
            int cb = rnd * 64 + nhi * 32;
            gemm16x32(sm + F_BUFB, sm + F_W4, mb, cb, lane, c);
            #pragma unroll
            for (int n8 = 0; n8 < 4; n8++) {
                int cc = cb + n8 * 8 + (lane & 3) * 2;
                float b0 = sm[F_B4 + cc], b1 = sm[F_B4 + cc + 1];
                int ai = rnd * 16 + n8 * 4;
                acc[ai + 0] += ev0 * fmaxf(c[n8][0] + b0, 0.f);
                acc[ai + 1] += ev0 * fmaxf(c[n8][1] + b1, 0.f);
                acc[ai + 2] += ev1 * fmaxf(c[n8][2] + b0, 0.f);
                acc[ai + 3] += ev1 * fmaxf(c[n8][3] + b1, 0.f);
            }
        }
    }

    // ---- write this group's partial tile ----
    {
        size_t base0 = ((size_t)g * V_PTS + v0 + r0) * 256;
        size_t base1 = ((size_t)g * V_PTS + v0 + r0 + 8) * 256;
        #pragma unroll
        for (int rnd = 0; rnd < 4; rnd++) {
            #pragma unroll
            for (int n8 = 0; n8 < 4; n8++) {
                int cc = rnd * 64 + nhi * 32 + n8 * 8 + (lane & 3) * 2;
                int ai = rnd * 16 + n8 * 4;
                *(float2*)&g_fpart[base0 + cc] = make_float2(acc[ai + 0], acc[ai + 1]);
                *(float2*)&g_fpart[base1 + cc] = make_float2(acc[ai + 2], acc[ai + 3]);
            }
        }
    }
}

// =====================================================================
// Kernel D: reduce partials + NeRF head
// =====================================================================
__global__ void head_kernel(const float* __restrict__ Wc1, const float* __restrict__ bc1,
                            const float* __restrict__ Wc2, const float* __restrict__ bc2,
                            const float* __restrict__ Wd1, const float* __restrict__ bd1,
                            float* __restrict__ out)
{
    int v = blockIdx.x;
    int t = threadIdx.x;   // 64 threads
    __shared__ float f_s[256];
    __shared__ float netc_s[64];

    {
        float4 s = make_float4(0.f, 0.f, 0.f, 0.f);
        #pragma unroll
        for (int g2 = 0; g2 < NG; g2++) {
            float4 p = *(const float4*)&g_fpart[((size_t)g2 * V_PTS + v) * 256 + t * 4];
            s.x += p.x; s.y += p.y; s.z += p.z; s.w += p.w;
        }
        *(float4*)&f_s[t * 4] = s;
    }
    __syncthreads();

    {
        float a0 = 0.f, a1 = 0.f, a2 = 0.f, a3 = 0.f;
        #pragma unroll 8
        for (int c = 0; c < 256; c += 4) {
            a0 += f_s[c + 0] * Wc1[(c + 0) * 64 + t];
            a1 += f_s[c + 1] * Wc1[(c + 1) * 64 + t];
            a2 += f_s[c + 2] * Wc1[(c + 2) * 64 + t];
            a3 += f_s[c + 3] * Wc1[(c + 3) * 64 + t];
        }
        netc_s[t] = fmaxf(bc1[t] + ((a0 + a1) + (a2 + a3)), 0.f);
    }
    __syncthreads();

    if (t < 3) {
        float r = bc2[t];
        #pragma unroll 8
        for (int j = 0; j < 64; j++) r += netc_s[j] * Wc2[j * 3 + t];
        out[OFF_C + v * 3 + t] = r;
    } else if (t == 3) {
        float r0 = 0.f, r1 = 0.f, r2 = 0.f, r3 = 0.f;
        #pragma unroll 8
        for (int c = 0; c < 256; c += 4) {
            r0 += f_s[c + 0] * Wd1[c + 0];
            r1 += f_s[c + 1] * Wd1[c + 1];
            r2 += f_s[c + 2] * Wd1[c + 2];
            r3 += f_s[c + 3] * Wd1[c + 3];
        }
        out[OFF_D + v] = fmaxf(bd1[0] + ((r0 + r1) + (r2 + r3)), 0.f);
    }
}

// =====================================================================
extern "C" void kernel_launch(void* const* d_in, const int* in_sizes, int n_in,
                              void* d_out, int out_size)
{
    const float* poses = (const float*)d_in[0];
    const float* t_ped = (const float*)d_in[1];
    const float* w     = (const float*)d_in[2];
    const float* wpts  = (const float*)d_in[3];
    const float* nodes = (const float*)d_in[4];
    const float* lc    = (const float*)d_in[5];
    const float *Wec1 = (const float*)d_in[6],  *bec1 = (const float*)d_in[7];
    const float *Wec21= (const float*)d_in[8],  *bec21= (const float*)d_in[9];
    const float *Wec22= (const float*)d_in[10], *bec22= (const float*)d_in[11];
    const float *Wdc1 = (const float*)d_in[12], *bdc1 = (const float*)d_in[13];
    const float *Wdc21= (const float*)d_in[14], *bdc21= (const float*)d_in[15];
    const float *Wdc22= (const float*)d_in[16], *bdc22= (const float*)d_in[17];
    const float *Wf1  = (const float*)d_in[18], *bf1  = (const float*)d_in[19];
    const float *Wf2  = (const float*)d_in[20], *bf2  = (const float*)d_in[21];
    const float *Wf3  = (const float*)d_in[22], *bf3  = (const float*)d_in[23];
    const float *Wf4  = (const float*)d_in[24], *bf4  = (const float*)d_in[25];
    const float *Wc1  = (const float*)d_in[26], *bc1  = (const float*)d_in[27];
    const float *Wc2  = (const float*)d_in[28], *bc2  = (const float*)d_in[29];
    const float *Wd1  = (const float*)d_in[30], *bd1  = (const float*)d_in[31];
    float* out = (float*)d_out;

    setup_kernel<<<N_NODES, 128>>>(poses, t_ped, w,
                                   Wec1, bec1, Wec21, bec21, Wec22, bec22,
                                   Wdc1, bdc1, Wdc21, bdc21, Wdc22, bdc22,
                                   Wf1, bf1, out);
    bweight_kernel<<<V_PTS / 256, 256>>>(wpts, nodes);
    prepack_kernel<<<N_NODES, 256>>>(Wf1, Wf2, Wf3, Wf4);

    cudaFuncSetAttribute(field_kernel,
                         cudaFuncAttributeMaxDynamicSharedMemorySize,
                         F_TOT * (int)sizeof(float));
    field_kernel<<<dim3(V_PTS / 128, NG), 512, F_TOT * sizeof(float)>>>(lc, bf2, bf3, bf4);

    head_kernel<<<V_PTS, 64>>>(Wc1, bc1, Wc2, bc2, Wd1, bd1, out);
}